// round 14
// baseline (speedup 1.0000x reference)
#include <cuda_runtime.h>
#include <cuda_bf16.h>
#include <cuda_fp16.h>
#include <cstdint>
#include <float.h>

#define BATCH 2
#define NSEQ  2048
#define DIM   512
#define H     8
#define DH    64
#define INNER 512
#define M_TOT 4096
#define QKV_N 1536
#define QSCALE 0.18033688f   /* 0.125 * log2(e) */

// ---------------- device scratch (allocation-free) --------------------------
__device__ __align__(16) __half g_xf[M_TOT*DIM];         // x fp16
__device__ __align__(16) __half g_wqf[QKV_N*DIM];        // w_qkv^T fp16 [N][K]
__device__ __align__(16) __half g_wof[DIM*INNER];        // w_out^T fp16 [N][K]
__device__ __align__(16) __half g_qf[BATCH*H*NSEQ*DH];   // [bh][n][d], pre-scaled
__device__ __align__(16) __half g_kf[BATCH*H*NSEQ*DH];   // [bh][n][d]
__device__ __align__(16) __half g_vf[BATCH*H*DH*NSEQ];   // [bh][d][n] (V^T)
__device__ __align__(16) __half g_ao[M_TOT*INNER];       // [b*n][h*d]

// ---------------- helpers ---------------------------------------------------
#define MMAH(d, a, b0, b1)                                                     \
    asm volatile("mma.sync.aligned.m16n8k16.row.col.f32.f16.f16.f32 "          \
        "{%0,%1,%2,%3},{%4,%5,%6,%7},{%8,%9},{%0,%1,%2,%3};"                   \
        : "+f"((d)[0]), "+f"((d)[1]), "+f"((d)[2]), "+f"((d)[3])               \
        : "r"((a)[0]), "r"((a)[1]), "r"((a)[2]), "r"((a)[3]),                  \
          "r"(b0), "r"(b1))

#define LDM4(r, a)                                                             \
    asm volatile("ldmatrix.sync.aligned.m8n8.x4.shared.b16 {%0,%1,%2,%3}, [%4];" \
        : "=r"((r)[0]), "=r"((r)[1]), "=r"((r)[2]), "=r"((r)[3]) : "r"(a))

__device__ __forceinline__ float ex2(float x) {
    float r;
    asm("ex2.approx.f32 %0, %1;" : "=f"(r) : "f"(x));
    return r;
}
__device__ __forceinline__ uint32_t ex2h2(uint32_t x) {
    uint32_t r;
    asm("ex2.approx.f16x2 %0, %1;" : "=r"(r) : "r"(x));
    return r;
}
__device__ __forceinline__ uint32_t packh2(float a, float b) {
    __half2 h = __floats2half2_rn(a, b);
    return *reinterpret_cast<uint32_t*>(&h);
}
__device__ __forceinline__ uint32_t smem_u32(const void* p) {
    uint32_t a;
    asm("{ .reg .u64 t; cvta.to.shared.u64 t, %1; cvt.u32.u64 %0, t; }"
        : "=r"(a) : "l"(p));
    return a;
}
__device__ __forceinline__ void cp16(uint32_t d, const void* s) {
    asm volatile("cp.async.cg.shared.global [%0], [%1], 16;"
                 :: "r"(d), "l"(s) : "memory");
}
#define CP_COMMIT() asm volatile("cp.async.commit_group;" ::: "memory")
#define CP_WAIT1()  asm volatile("cp.async.wait_group 1;" ::: "memory")
#define CP_WAIT2()  asm volatile("cp.async.wait_group 2;" ::: "memory")

// ---------------- merged prep kernel ----------------------------------------
#define NBX  (M_TOT*DIM/1024)        /* 2048 */
#define NBWQ ((QKV_N/32)*(DIM/32))   /* 768 */
#define NBWO ((DIM/32)*(INNER/32))   /* 256 */

__global__ void __launch_bounds__(256) prep_all(
    const float* __restrict__ x,
    const float* __restrict__ w_qkv,
    const float* __restrict__ w_out)
{
    __shared__ float t[32][33];
    const int b = blockIdx.x, tid = threadIdx.x;

    if (b < NBX) {
        int i = (b * 256 + tid) * 4;
        float4 v = *(const float4*)&x[i];
        uint2 o;
        o.x = packh2(v.x, v.y);
        o.y = packh2(v.z, v.w);
        *(uint2*)&g_xf[i] = o;
        return;
    }

    const float* src; __half* dst; int R, C, l;
    if (b < NBX + NBWQ) {
        l = b - NBX; src = w_qkv; dst = g_wqf; R = DIM; C = QKV_N;
    } else {
        l = b - NBX - NBWQ; src = w_out; dst = g_wof; R = INNER; C = DIM;
    }
    int bx = l % (C / 32), by = l / (C / 32);
    int c0 = bx * 32, r0 = by * 32;
    int xx = tid & 31, yy = tid >> 5;   // 32 x 8
    #pragma unroll
    for (int j = 0; j < 32; j += 8)
        t[yy + j][xx] = src[(size_t)(r0 + yy + j) * C + c0 + xx];
    __syncthreads();
    #pragma unroll
    for (int j = 0; j < 32; j += 8)
        dst[(size_t)(c0 + yy + j) * R + r0 + xx] = __float2half(t[xx][yy + j]);
}

// ---------------- qkv GEMM: 128x128, BK=64, 3-stage, 256 thr ----------------
#define GSTR 72
#define GARR 18432                    /* 128*GSTR*2 bytes per array */
#define GSTAGE 36864                  /* 2 arrays */
#define CSTR 132
#define GEMM_SMEM 110592              /* 3 stages; Cs (67584) reuses */

__global__ void __launch_bounds__(256, 2) gemm_mma(
    const __half* __restrict__ Ah, const __half* __restrict__ Bh, int K)
{
    extern __shared__ char smraw[];
    const uint32_t sb = smem_u32(smraw);
    float* Cs = (float*)smraw;

    const int tid = threadIdx.x, lane = tid & 31, wid = tid >> 5;
    const int wm = (wid & 3) * 32, wn = (wid >> 2) * 64;
    const int m0 = blockIdx.y * 128, n0 = blockIdx.x * 128;
    const int lr = lane >> 2, lc = (lane & 3) * 2;
    const int nCh = K >> 6;

    const int a_row = (lane & 7) + ((lane >> 3) & 1) * 8;
    const int a_kof = (lane >> 4) * 8;
    const int b_row = (lane & 7) + (lane >> 4) * 8;
    const int b_kof = ((lane >> 3) & 1) * 8;

    float acc[2][8][4];
    #pragma unroll
    for (int i = 0; i < 2; i++)
        #pragma unroll
        for (int j = 0; j < 8; j++)
            #pragma unroll
            for (int e = 0; e < 4; e++) acc[i][j][e] = 0.f;

    auto load_stage = [&](int st, int k0) {
        uint32_t base = sb + st * GSTAGE;
        #pragma unroll
        for (int p = 0; p < 4; p++) {
            int id = tid + p * 256;
            int r = id >> 3, sg = (id & 7) * 8;
            uint32_t so = r * (GSTR * 2) + sg * 2;
            cp16(base + 0 * GARR + so, Ah + (size_t)(m0 + r) * K + k0 + sg);
            cp16(base + 1 * GARR + so, Bh + (size_t)(n0 + r) * K + k0 + sg);
        }
    };

    load_stage(0, 0);
    CP_COMMIT();
    if (nCh > 1) load_stage(1, 64);
    CP_COMMIT();

    for (int c = 0; c < nCh; ++c) {
        CP_WAIT1();
        __syncthreads();
        if (c + 2 < nCh) load_stage((c + 2) % 3, (c + 2) << 6);
        CP_COMMIT();

        const uint32_t stb = sb + (c % 3) * GSTAGE;

        #pragma unroll
        for (int kc = 0; kc < 64; kc += 16) {
            uint32_t ah[2][4];
            #pragma unroll
            for (int mt = 0; mt < 2; mt++) {
                uint32_t ao_ = stb + ((wm + mt * 16 + a_row) * GSTR + kc + a_kof) * 2;
                LDM4(ah[mt], ao_);
            }
            #pragma unroll
            for (int nt2 = 0; nt2 < 4; nt2++) {
                uint32_t bo = stb + ((wn + nt2 * 16 + b_row) * GSTR + kc + b_kof) * 2;
                uint32_t bh4[4];
                LDM4(bh4, bo + 1 * GARR);
                const int n0t = nt2 * 2, n1t = nt2 * 2 + 1;
                MMAH(acc[0][n0t], ah[0], bh4[0], bh4[1]);
                MMAH(acc[1][n0t], ah[1], bh4[0], bh4[1]);
                MMAH(acc[0][n1t], ah[0], bh4[2], bh4[3]);
                MMAH(acc[1][n1t], ah[1], bh4[2], bh4[3]);
            }
        }
    }
    __syncthreads();

    // stage C in smem (fp32)
    #pragma unroll
    for (int mt = 0; mt < 2; mt++)
        #pragma unroll
        for (int nt = 0; nt < 8; nt++)
            #pragma unroll
            for (int e = 0; e < 4; e++) {
                int r = wm + mt * 16 + lr + (e >> 1) * 8;
                int c = wn + nt * 8 + lc + (e & 1);
                Cs[r * CSTR + c] = acc[mt][nt][e];
            }
    __syncthreads();

    // qkv scatter epilogue
    const int t = n0 >> 9, sec = n0 & 511, head0 = sec >> 6;
    const int bb = m0 >> 11, nbase = m0 & (NSEQ - 1);
    if (t < 2) {
        __half* dst = (t == 0) ? g_qf : g_kf;
        const float qs = (t == 0) ? QSCALE : 1.0f;   // fold softmax scale into Q
        #pragma unroll
        for (int p = 0; p < 32; p++) {
            int w = tid + p * 256;
            int row = w >> 6, j = w & 63;
            int head = head0 + (j >> 5), ji = j & 31;
            float c0 = Cs[row * CSTR + 2 * j] * qs;
            float c1 = Cs[row * CSTR + 2 * j + 1] * qs;
            size_t base = ((size_t)(bb * 8 + head) * NSEQ + nbase + row) * DH;
            ((uint32_t*)(dst + base))[ji] = packh2(c0, c1);
        }
    } else {
        // V transposed fp16: [bh][d][n]
        #pragma unroll
        for (int cit = 0; cit < 16; cit++) {
            int col = wid * 16 + cit;
            int head = head0 + (col >> 6), d = col & 63;
            int r0 = lane * 4;
            float v0 = Cs[(r0 + 0) * CSTR + col];
            float v1 = Cs[(r0 + 1) * CSTR + col];
            float v2 = Cs[(r0 + 2) * CSTR + col];
            float v3 = Cs[(r0 + 3) * CSTR + col];
            size_t base = ((size_t)(bb * 8 + head) * DH + d) * NSEQ + nbase + r0;
            ((uint32_t*)(g_vf + base))[0] = packh2(v0, v1);
            ((uint32_t*)(g_vf + base))[1] = packh2(v2, v3);
        }
    }
}

// ---------------- out GEMM: 128x128 tile, 512 threads (16 warps) ------------
// Same grid (4, 32) = 128 CTAs, but 16 warps/CTA -> 4 warps/SMSP.
__global__ void __launch_bounds__(512, 1) out_gemm512(
    const __half* __restrict__ Ah, const __half* __restrict__ Bh,
    int K, const float* __restrict__ bias, float* __restrict__ outp)
{
    extern __shared__ char smraw[];
    const uint32_t sb = smem_u32(smraw);
    float* Cs = (float*)smraw;

    const int tid = threadIdx.x, lane = tid & 31, wid = tid >> 5;
    const int wm = (wid & 7) * 16, wn = (wid >> 3) * 64;
    const int m0 = blockIdx.y * 128, n0 = blockIdx.x * 128;
    const int lr = lane >> 2, lc = (lane & 3) * 2;
    const int nCh = K >> 6;

    const int a_row = (lane & 7) + ((lane >> 3) & 1) * 8;
    const int a_kof = (lane >> 4) * 8;
    const int b_row = (lane & 7) + (lane >> 4) * 8;
    const int b_kof = ((lane >> 3) & 1) * 8;

    float acc[8][4];
    #pragma unroll
    for (int j = 0; j < 8; j++)
        #pragma unroll
        for (int e = 0; e < 4; e++) acc[j][e] = 0.f;

    auto load_stage = [&](int st, int k0) {
        uint32_t base = sb + st * GSTAGE;
        #pragma unroll
        for (int p = 0; p < 2; p++) {
            int id = tid + p * 512;
            int r = id >> 3, sg = (id & 7) * 8;
            uint32_t so = r * (GSTR * 2) + sg * 2;
            cp16(base + 0 * GARR + so, Ah + (size_t)(m0 + r) * K + k0 + sg);
            cp16(base + 1 * GARR + so, Bh + (size_t)(n0 + r) * K + k0 + sg);
        }
    };

    load_stage(0, 0);
    CP_COMMIT();
    if (nCh > 1) load_stage(1, 64);
    CP_COMMIT();

    for (int c = 0; c < nCh; ++c) {
        CP_WAIT1();
        __syncthreads();
        if (c + 2 < nCh) load_stage((c + 2) % 3, (c + 2) << 6);
        CP_COMMIT();

        const uint32_t stb = sb + (c % 3) * GSTAGE;

        #pragma unroll
        for (int kc = 0; kc < 64; kc += 16) {
            uint32_t ah4[4];
            LDM4(ah4, stb + ((wm + a_row) * GSTR + kc + a_kof) * 2);
            #pragma unroll
            for (int nt2 = 0; nt2 < 4; nt2++) {
                uint32_t bo = stb + ((wn + nt2 * 16 + b_row) * GSTR + kc + b_kof) * 2;
                uint32_t bh4[4];
                LDM4(bh4, bo + 1 * GARR);
                MMAH(acc[nt2 * 2],     ah4, bh4[0], bh4[1]);
                MMAH(acc[nt2 * 2 + 1], ah4, bh4[2], bh4[3]);
            }
        }
    }
    __syncthreads();

    // stage C in smem (fp32)
    #pragma unroll
    for (int nt = 0; nt < 8; nt++)
        #pragma unroll
        for (int e = 0; e < 4; e++) {
            int r = wm + lr + (e >> 1) * 8;
            int c = wn + nt * 8 + lc + (e & 1);
            Cs[r * CSTR + c] = acc[nt][e];
        }
    __syncthreads();

    #pragma unroll
    for (int p = 0; p < 8; p++) {
        int w = tid + p * 512;
        int row = w >> 5, q4 = (w & 31) * 4;
        float4 o;
        o.x = Cs[row * CSTR + q4 + 0] + bias[n0 + q4 + 0];
        o.y = Cs[row * CSTR + q4 + 1] + bias[n0 + q4 + 1];
        o.z = Cs[row * CSTR + q4 + 2] + bias[n0 + q4 + 2];
        o.w = Cs[row * CSTR + q4 + 3] + bias[n0 + q4 + 3];
        *(float4*)&outp[(size_t)(m0 + row) * DIM + n0 + q4] = o;
    }
}

// ---------------- attention: fp16, 128-q tile, 8 warps, 4-stage cp.async ----
// Q pre-scaled; full tiles use ex2.approx.f16x2 (half the MUFU ops).
#define ASTR 72
#define AQ_BYTES (128 * ASTR * 2)         /* 18432 */
#define AARR (64 * ASTR * 2)              /* 9216 */
#define ASTAGE (2 * AARR)                 /* 18432 */
#define AST0 AQ_BYTES
#define ATT_SMEM (AST0 + 4 * ASTAGE)      /* 92160 */
#define AOSTR 68

__global__ void __launch_bounds__(256, 2) attn_mma()
{
    extern __shared__ char smraw[];
    const uint32_t sb = smem_u32(smraw);
    __half* Qf = (__half*)smraw;
    float* OS = (float*)(smraw + AST0);   // epilogue reuse (34816 <= 73728)

    const int tid = threadIdx.x, lane = tid & 31, wid = tid >> 5;
    const int bh = blockIdx.y;
    const int qbase = blockIdx.x * 128;
    const int lr = lane >> 2, lc = (lane & 3) * 2;

    const int a_row = (lane & 7) + ((lane >> 3) & 1) * 8;
    const int a_kof = (lane >> 4) * 8;
    const int b_row = (lane & 7) + (lane >> 4) * 8;
    const int b_kof = ((lane >> 3) & 1) * 8;

    const __half* gQ = g_qf + (size_t)bh * NSEQ * DH;
    const __half* gK = g_kf + (size_t)bh * NSEQ * DH;
    const __half* gV = g_vf + (size_t)bh * DH * NSEQ;

    // kept key-tile list + full-unmasked flag (uniform per block)
    int list[32]; int full[32]; int nk = 0;
    #pragma unroll
    for (int kt = 0; kt < 32; kt++) {
        int diff = qbase - kt * 64;
        int lo = diff - 63, hi = diff + 127;
        int mn = lo > 0 ? lo : (hi < 0 ? -hi : 0);
        int alo = lo < 0 ? -lo : lo, ahi = hi < 0 ? -hi : hi;
        int mx = alo > ahi ? alo : ahi;
        if (!(mn > 256 && mx <= 1024)) {
            list[nk] = kt;
            full[nk] = (mx <= 256 || mn > 1024) ? 1 : 0;
            nk++;
        }
    }

    auto load_kv = [&](int st, int kt) {
        const int kb = kt * 64;
        uint32_t base = sb + AST0 + st * ASTAGE;
        #pragma unroll
        for (int p = 0; p < 2; p++) {
            int id = tid + p * 256;
            int r = id >> 3, sg = (id & 7) * 8;
            uint32_t so = (r * ASTR + sg) * 2;
            cp16(base + 0 * AARR + so, gK + (size_t)(kb + r) * DH + sg);
            cp16(base + 1 * AARR + so, gV + (size_t)r * NSEQ + kb + sg);
        }
    };

    // load Q tile + first three K/V stages
    #pragma unroll
    for (int p = 0; p < 4; p++) {
        int id = tid + p * 256;
        int r = id >> 3, sg = (id & 7) * 8;
        *(uint4*)&Qf[r * ASTR + sg] = *(const uint4*)&gQ[(size_t)(qbase + r) * DH + sg];
    }
    load_kv(0, list[0]);
    CP_COMMIT();
    if (nk > 1) load_kv(1, list[1]);
    CP_COMMIT();
    if (nk > 2) load_kv(2, list[2]);
    CP_COMMIT();
    __syncthreads();

    // persistent Q fragments
    uint32_t qf[4][4];
    #pragma unroll
    for (int t = 0; t < 4; t++) {
        uint32_t qa = sb + ((wid * 16 + a_row) * ASTR + t * 16 + a_kof) * 2;
        LDM4(qf[t], qa);
    }

    float o[8][4];
    #pragma unroll
    for (int i = 0; i < 8; i++)
        #pragma unroll
        for (int e = 0; e < 4; e++) o[i][e] = 0.f;
    float l0 = 0.f, l1 = 0.f;

    for (int i = 0; i < nk; i++) {
        CP_WAIT2();
        __syncthreads();
        if (i + 3 < nk) load_kv((i + 3) & 3, list[i + 3]);
        CP_COMMIT();

        const int kb = list[i] * 64;
        const uint32_t stb = sb + AST0 + (i & 3) * ASTAGE;

        // S = Q K^T  (Q pre-scaled: S is log2-domain logits)
        float s[8][4];
        #pragma unroll
        for (int j = 0; j < 8; j++)
            #pragma unroll
            for (int e = 0; e < 4; e++) s[j][e] = 0.f;
        #pragma unroll
        for (int t = 0; t < 4; t++) {
            #pragma unroll
            for (int nt2 = 0; nt2 < 4; nt2++) {
                uint32_t k4[4];
                LDM4(k4, stb + ((nt2 * 16 + b_row) * ASTR + t * 16 + b_kof) * 2);
                MMAH(s[2*nt2],     qf[t], k4[0], k4[1]);
                MMAH(s[2*nt2 + 1], qf[t], k4[2], k4[3]);
            }
        }

        // exp2 + row sums; P kept packed fp16 for the PV MMA
        uint32_t pp[8][2];
        float rs0 = 0.f, rs1 = 0.f;
        if (full[i]) {
            #pragma unroll
            for (int nt = 0; nt < 8; nt++) {
                uint32_t a01 = packh2(s[nt][0], s[nt][1]);
                uint32_t a23 = packh2(s[nt][2], s[nt][3]);
                pp[nt][0] = ex2h2(a01);
                pp[nt][1] = ex2h2(a23);
                float2 f0 = __half22float2(*(__half2*)&pp[nt][0]);
                float2 f1 = __half22float2(*(__half2*)&pp[nt][1]);
                rs0 += f0.x + f0.y;
                rs1 += f1.x + f1.y;
            }
        } else {
            const int qr = qbase + wid * 16 + lr;
            #pragma unroll
            for (int nt = 0; nt < 8; nt++) {
                int c = kb + nt * 8 + lc;
                float p[4];
                #pragma unroll
                for (int e = 0; e < 4; e++) {
                    int qi = qr + (e >> 1) * 8;
                    int kj = c + (e & 1);
                    int d = qi - kj; if (d < 0) d = -d;
                    p[e] = (d > 256 && d <= 1024) ? 0.f : ex2(s[nt][e]);
                    if (e < 2) rs0 += p[e]; else rs1 += p[e];
                }
                pp[nt][0] = packh2(p[0], p[1]);
                pp[nt][1] = packh2(p[2], p[3]);
            }
        }
        rs0 += __shfl_xor_sync(0xffffffffu, rs0, 1);
        rs0 += __shfl_xor_sync(0xffffffffu, rs0, 2);
        rs1 += __shfl_xor_sync(0xffffffffu, rs1, 1);
        rs1 += __shfl_xor_sync(0xffffffffu, rs1, 2);
        l0 += rs0; l1 += rs1;

        // O += P V
        #pragma unroll
        for (int t = 0; t < 4; t++) {
            uint32_t ph[4];
            ph[0] = pp[2*t][0];
            ph[1] = pp[2*t][1];
            ph[2] = pp[2*t+1][0];
            ph[3] = pp[2*t+1][1];
            #pragma unroll
            for (int dt2 = 0; dt2 < 4; dt2++) {
                uint32_t vo = ((dt2 * 16 + b_row) * ASTR + t * 16 + b_kof) * 2;
                uint32_t vh4[4];
                LDM4(vh4, stb + 1 * AARR + vo);
                MMAH(o[2*dt2],   ph, vh4[0], vh4[1]);
                MMAH(o[2*dt2+1], ph, vh4[2], vh4[3]);
            }
        }
    }
    __syncthreads();

    // normalize, stage, coalesced fp16 store
    float inv0 = 1.f / l0, inv1 = 1.f / l1;
    #pragma unroll
    for (int dt = 0; dt < 8; dt++)
        #pragma unroll
        for (int e = 0; e < 4; e++) {
            int r = wid * 16 + lr + (e >> 1) * 8;
            int c = dt * 8 + lc + (e & 1);
            OS[r * AOSTR + c] = o[dt][e] * ((e < 2) ? inv0 : inv1);
        }
    __syncthreads();

    const int bb = bh >> 3, hh = bh & 7;
    #pragma unroll
    for (int p = 0; p < 16; p++) {
        int w = tid + p * 256;
        int row = w >> 5, j = w & 31;
        float c0 = OS[row * AOSTR + 2 * j];
        float c1 = OS[row * AOSTR + 2 * j + 1];
        size_t base = ((size_t)(bb * NSEQ + qbase + row)) * INNER + hh * DH + 2 * j;
        *(uint32_t*)(g_ao + base) = packh2(c0, c1);
    }
}

// ---------------------------------------------------------------------------
extern "C" void kernel_launch(void* const* d_in, const int* in_sizes, int n_in,
                              void* d_out, int out_size)
{
    (void)in_sizes; (void)n_in; (void)out_size;
    const float* x     = (const float*)d_in[0];
    const float* w_qkv = (const float*)d_in[1];
    const float* w_out = (const float*)d_in[2];
    const float* b_out = (const float*)d_in[3];
    float* out = (float*)d_out;

    __half *xf, *wqf, *wof, *ao;
    cudaGetSymbolAddress((void**)&xf,  g_xf);
    cudaGetSymbolAddress((void**)&wqf, g_wqf);
    cudaGetSymbolAddress((void**)&wof, g_wof);
    cudaGetSymbolAddress((void**)&ao,  g_ao);

    cudaFuncSetAttribute(gemm_mma,   cudaFuncAttributeMaxDynamicSharedMemorySize, GEMM_SMEM);
    cudaFuncSetAttribute(out_gemm512, cudaFuncAttributeMaxDynamicSharedMemorySize, GEMM_SMEM);
    cudaFuncSetAttribute(attn_mma,   cudaFuncAttributeMaxDynamicSharedMemorySize, ATT_SMEM);

    prep_all<<<NBX + NBWQ + NBWO, 256>>>(x, w_qkv, w_out);

    gemm_mma<<<dim3(QKV_N/128, M_TOT/128), 256, GEMM_SMEM>>>(xf, wqf, DIM);

    attn_mma<<<dim3(NSEQ/128, BATCH*H), 256, ATT_SMEM>>>();

    out_gemm512<<<dim3(DIM/128, M_TOT/128), 512, GEMM_SMEM>>>(
        ao, wof, INNER, b_out, out);
}

// round 15
// speedup vs baseline: 1.0165x; 1.0165x over previous
#include <cuda_runtime.h>
#include <cuda_bf16.h>
#include <cuda_fp16.h>
#include <cstdint>
#include <float.h>

#define BATCH 2
#define NSEQ  2048
#define DIM   512
#define H     8
#define DH    64
#define INNER 512
#define M_TOT 4096
#define QKV_N 1536
#define QSCALE 0.18033688f   /* 0.125 * log2(e) */

// ---------------- device scratch (allocation-free) --------------------------
__device__ __align__(16) __half g_xf[M_TOT*DIM];         // x fp16
__device__ __align__(16) __half g_wqf[QKV_N*DIM];        // w_qkv^T fp16 [N][K]
__device__ __align__(16) __half g_wof[DIM*INNER];        // w_out^T fp16 [N][K]
__device__ __align__(16) __half g_qf[BATCH*H*NSEQ*DH];   // [bh][n][d], pre-scaled
__device__ __align__(16) __half g_kf[BATCH*H*NSEQ*DH];   // [bh][n][d]
__device__ __align__(16) __half g_vf[BATCH*H*DH*NSEQ];   // [bh][d][n] (V^T)
__device__ __align__(16) __half g_ao[M_TOT*INNER];       // [b*n][h*d]

// ---------------- helpers ---------------------------------------------------
#define MMAH(d, a, b0, b1)                                                     \
    asm volatile("mma.sync.aligned.m16n8k16.row.col.f32.f16.f16.f32 "          \
        "{%0,%1,%2,%3},{%4,%5,%6,%7},{%8,%9},{%0,%1,%2,%3};"                   \
        : "+f"((d)[0]), "+f"((d)[1]), "+f"((d)[2]), "+f"((d)[3])               \
        : "r"((a)[0]), "r"((a)[1]), "r"((a)[2]), "r"((a)[3]),                  \
          "r"(b0), "r"(b1))

#define LDM4(r, a)                                                             \
    asm volatile("ldmatrix.sync.aligned.m8n8.x4.shared.b16 {%0,%1,%2,%3}, [%4];" \
        : "=r"((r)[0]), "=r"((r)[1]), "=r"((r)[2]), "=r"((r)[3]) : "r"(a))

__device__ __forceinline__ float ex2(float x) {
    float r;
    asm("ex2.approx.f32 %0, %1;" : "=f"(r) : "f"(x));
    return r;
}
__device__ __forceinline__ uint32_t ex2h2(uint32_t x) {
    uint32_t r;
    asm("ex2.approx.f16x2 %0, %1;" : "=r"(r) : "r"(x));
    return r;
}
__device__ __forceinline__ uint32_t packh2(float a, float b) {
    __half2 h = __floats2half2_rn(a, b);
    return *reinterpret_cast<uint32_t*>(&h);
}
__device__ __forceinline__ uint32_t smem_u32(const void* p) {
    uint32_t a;
    asm("{ .reg .u64 t; cvta.to.shared.u64 t, %1; cvt.u32.u64 %0, t; }"
        : "=r"(a) : "l"(p));
    return a;
}
__device__ __forceinline__ void cp16(uint32_t d, const void* s) {
    asm volatile("cp.async.cg.shared.global [%0], [%1], 16;"
                 :: "r"(d), "l"(s) : "memory");
}
#define CP_COMMIT() asm volatile("cp.async.commit_group;" ::: "memory")
#define CP_WAIT1()  asm volatile("cp.async.wait_group 1;" ::: "memory")
#define CP_WAIT2()  asm volatile("cp.async.wait_group 2;" ::: "memory")

// ---------------- merged prep kernel ----------------------------------------
#define NBX  (M_TOT*DIM/1024)        /* 2048 */
#define NBWQ ((QKV_N/32)*(DIM/32))   /* 768 */
#define NBWO ((DIM/32)*(INNER/32))   /* 256 */

__global__ void __launch_bounds__(256) prep_all(
    const float* __restrict__ x,
    const float* __restrict__ w_qkv,
    const float* __restrict__ w_out)
{
    __shared__ float t[32][33];
    const int b = blockIdx.x, tid = threadIdx.x;

    if (b < NBX) {
        int i = (b * 256 + tid) * 4;
        float4 v = *(const float4*)&x[i];
        uint2 o;
        o.x = packh2(v.x, v.y);
        o.y = packh2(v.z, v.w);
        *(uint2*)&g_xf[i] = o;
        return;
    }

    const float* src; __half* dst; int R, C, l;
    if (b < NBX + NBWQ) {
        l = b - NBX; src = w_qkv; dst = g_wqf; R = DIM; C = QKV_N;
    } else {
        l = b - NBX - NBWQ; src = w_out; dst = g_wof; R = INNER; C = DIM;
    }
    int bx = l % (C / 32), by = l / (C / 32);
    int c0 = bx * 32, r0 = by * 32;
    int xx = tid & 31, yy = tid >> 5;   // 32 x 8
    #pragma unroll
    for (int j = 0; j < 32; j += 8)
        t[yy + j][xx] = src[(size_t)(r0 + yy + j) * C + c0 + xx];
    __syncthreads();
    #pragma unroll
    for (int j = 0; j < 32; j += 8)
        dst[(size_t)(c0 + yy + j) * R + r0 + xx] = __float2half(t[xx][yy + j]);
}

// ---------------- qkv GEMM: 128x128, BK=64, 3-stage, 256 thr, 2 CTA/SM ------
#define GSTR 72
#define GARR 18432                    /* 128*GSTR*2 bytes per array */
#define GSTAGE 36864                  /* 2 arrays */
#define CSTR 132
#define GEMM_SMEM 110592              /* 3 stages; Cs (67584) reuses */
#define OUT_SMEM 118784               /* padded > 228KB/2: forces 1 CTA/SM */

__global__ void __launch_bounds__(256, 2) gemm_mma(
    const __half* __restrict__ Ah, const __half* __restrict__ Bh, int K)
{
    extern __shared__ char smraw[];
    const uint32_t sb = smem_u32(smraw);
    float* Cs = (float*)smraw;

    const int tid = threadIdx.x, lane = tid & 31, wid = tid >> 5;
    const int wm = (wid & 3) * 32, wn = (wid >> 2) * 64;
    const int m0 = blockIdx.y * 128, n0 = blockIdx.x * 128;
    const int lr = lane >> 2, lc = (lane & 3) * 2;
    const int nCh = K >> 6;

    const int a_row = (lane & 7) + ((lane >> 3) & 1) * 8;
    const int a_kof = (lane >> 4) * 8;
    const int b_row = (lane & 7) + (lane >> 4) * 8;
    const int b_kof = ((lane >> 3) & 1) * 8;

    float acc[2][8][4];
    #pragma unroll
    for (int i = 0; i < 2; i++)
        #pragma unroll
        for (int j = 0; j < 8; j++)
            #pragma unroll
            for (int e = 0; e < 4; e++) acc[i][j][e] = 0.f;

    auto load_stage = [&](int st, int k0) {
        uint32_t base = sb + st * GSTAGE;
        #pragma unroll
        for (int p = 0; p < 4; p++) {
            int id = tid + p * 256;
            int r = id >> 3, sg = (id & 7) * 8;
            uint32_t so = r * (GSTR * 2) + sg * 2;
            cp16(base + 0 * GARR + so, Ah + (size_t)(m0 + r) * K + k0 + sg);
            cp16(base + 1 * GARR + so, Bh + (size_t)(n0 + r) * K + k0 + sg);
        }
    };

    load_stage(0, 0);
    CP_COMMIT();
    if (nCh > 1) load_stage(1, 64);
    CP_COMMIT();

    for (int c = 0; c < nCh; ++c) {
        CP_WAIT1();
        __syncthreads();
        if (c + 2 < nCh) load_stage((c + 2) % 3, (c + 2) << 6);
        CP_COMMIT();

        const uint32_t stb = sb + (c % 3) * GSTAGE;

        #pragma unroll
        for (int kc = 0; kc < 64; kc += 16) {
            uint32_t ah[2][4];
            #pragma unroll
            for (int mt = 0; mt < 2; mt++) {
                uint32_t ao_ = stb + ((wm + mt * 16 + a_row) * GSTR + kc + a_kof) * 2;
                LDM4(ah[mt], ao_);
            }
            #pragma unroll
            for (int nt2 = 0; nt2 < 4; nt2++) {
                uint32_t bo = stb + ((wn + nt2 * 16 + b_row) * GSTR + kc + b_kof) * 2;
                uint32_t bh4[4];
                LDM4(bh4, bo + 1 * GARR);
                const int n0t = nt2 * 2, n1t = nt2 * 2 + 1;
                MMAH(acc[0][n0t], ah[0], bh4[0], bh4[1]);
                MMAH(acc[1][n0t], ah[1], bh4[0], bh4[1]);
                MMAH(acc[0][n1t], ah[0], bh4[2], bh4[3]);
                MMAH(acc[1][n1t], ah[1], bh4[2], bh4[3]);
            }
        }
    }
    __syncthreads();

    // stage C in smem (fp32)
    #pragma unroll
    for (int mt = 0; mt < 2; mt++)
        #pragma unroll
        for (int nt = 0; nt < 8; nt++)
            #pragma unroll
            for (int e = 0; e < 4; e++) {
                int r = wm + mt * 16 + lr + (e >> 1) * 8;
                int c = wn + nt * 8 + lc + (e & 1);
                Cs[r * CSTR + c] = acc[mt][nt][e];
            }
    __syncthreads();

    // qkv scatter epilogue
    const int t = n0 >> 9, sec = n0 & 511, head0 = sec >> 6;
    const int bb = m0 >> 11, nbase = m0 & (NSEQ - 1);
    if (t < 2) {
        __half* dst = (t == 0) ? g_qf : g_kf;
        const float qs = (t == 0) ? QSCALE : 1.0f;   // fold softmax scale into Q
        #pragma unroll
        for (int p = 0; p < 32; p++) {
            int w = tid + p * 256;
            int row = w >> 6, j = w & 63;
            int head = head0 + (j >> 5), ji = j & 31;
            float c0 = Cs[row * CSTR + 2 * j] * qs;
            float c1 = Cs[row * CSTR + 2 * j + 1] * qs;
            size_t base = ((size_t)(bb * 8 + head) * NSEQ + nbase + row) * DH;
            ((uint32_t*)(dst + base))[ji] = packh2(c0, c1);
        }
    } else {
        // V transposed fp16: [bh][d][n]
        #pragma unroll
        for (int cit = 0; cit < 16; cit++) {
            int col = wid * 16 + cit;
            int head = head0 + (col >> 6), d = col & 63;
            int r0 = lane * 4;
            float v0 = Cs[(r0 + 0) * CSTR + col];
            float v1 = Cs[(r0 + 1) * CSTR + col];
            float v2 = Cs[(r0 + 2) * CSTR + col];
            float v3 = Cs[(r0 + 3) * CSTR + col];
            size_t base = ((size_t)(bb * 8 + head) * DH + d) * NSEQ + nbase + r0;
            ((uint32_t*)(g_vf + base))[0] = packh2(v0, v1);
            ((uint32_t*)(g_vf + base))[1] = packh2(v2, v3);
        }
    }
}

// ---------------- out GEMM: same structure, 1 CTA/SM (smem-padded) ----------
// 128 CTAs spread across 128 distinct SMs instead of 2-deep on 64.
__global__ void __launch_bounds__(256) out_gemm(
    const __half* __restrict__ Ah, const __half* __restrict__ Bh,
    int K, const float* __restrict__ bias, float* __restrict__ outp)
{
    extern __shared__ char smraw[];
    const uint32_t sb = smem_u32(smraw);
    float* Cs = (float*)smraw;

    const int tid = threadIdx.x, lane = tid & 31, wid = tid >> 5;
    const int wm = (wid & 3) * 32, wn = (wid >> 2) * 64;
    const int m0 = blockIdx.y * 128, n0 = blockIdx.x * 128;
    const int lr = lane >> 2, lc = (lane & 3) * 2;
    const int nCh = K >> 6;

    const int a_row = (lane & 7) + ((lane >> 3) & 1) * 8;
    const int a_kof = (lane >> 4) * 8;
    const int b_row = (lane & 7) + (lane >> 4) * 8;
    const int b_kof = ((lane >> 3) & 1) * 8;

    float acc[2][8][4];
    #pragma unroll
    for (int i = 0; i < 2; i++)
        #pragma unroll
        for (int j = 0; j < 8; j++)
            #pragma unroll
            for (int e = 0; e < 4; e++) acc[i][j][e] = 0.f;

    auto load_stage = [&](int st, int k0) {
        uint32_t base = sb + st * GSTAGE;
        #pragma unroll
        for (int p = 0; p < 4; p++) {
            int id = tid + p * 256;
            int r = id >> 3, sg = (id & 7) * 8;
            uint32_t so = r * (GSTR * 2) + sg * 2;
            cp16(base + 0 * GARR + so, Ah + (size_t)(m0 + r) * K + k0 + sg);
            cp16(base + 1 * GARR + so, Bh + (size_t)(n0 + r) * K + k0 + sg);
        }
    };

    load_stage(0, 0);
    CP_COMMIT();
    if (nCh > 1) load_stage(1, 64);
    CP_COMMIT();

    for (int c = 0; c < nCh; ++c) {
        CP_WAIT1();
        __syncthreads();
        if (c + 2 < nCh) load_stage((c + 2) % 3, (c + 2) << 6);
        CP_COMMIT();

        const uint32_t stb = sb + (c % 3) * GSTAGE;

        #pragma unroll
        for (int kc = 0; kc < 64; kc += 16) {
            uint32_t ah[2][4];
            #pragma unroll
            for (int mt = 0; mt < 2; mt++) {
                uint32_t ao_ = stb + ((wm + mt * 16 + a_row) * GSTR + kc + a_kof) * 2;
                LDM4(ah[mt], ao_);
            }
            #pragma unroll
            for (int nt2 = 0; nt2 < 4; nt2++) {
                uint32_t bo = stb + ((wn + nt2 * 16 + b_row) * GSTR + kc + b_kof) * 2;
                uint32_t bh4[4];
                LDM4(bh4, bo + 1 * GARR);
                const int n0t = nt2 * 2, n1t = nt2 * 2 + 1;
                MMAH(acc[0][n0t], ah[0], bh4[0], bh4[1]);
                MMAH(acc[1][n0t], ah[1], bh4[0], bh4[1]);
                MMAH(acc[0][n1t], ah[0], bh4[2], bh4[3]);
                MMAH(acc[1][n1t], ah[1], bh4[2], bh4[3]);
            }
        }
    }
    __syncthreads();

    // stage C in smem (fp32)
    #pragma unroll
    for (int mt = 0; mt < 2; mt++)
        #pragma unroll
        for (int nt = 0; nt < 8; nt++)
            #pragma unroll
            for (int e = 0; e < 4; e++) {
                int r = wm + mt * 16 + lr + (e >> 1) * 8;
                int c = wn + nt * 8 + lc + (e & 1);
                Cs[r * CSTR + c] = acc[mt][nt][e];
            }
    __syncthreads();

    #pragma unroll
    for (int p = 0; p < 16; p++) {
        int w = tid + p * 256;
        int row = w >> 5, q4 = (w & 31) * 4;
        float4 o;
        o.x = Cs[row * CSTR + q4 + 0] + bias[n0 + q4 + 0];
        o.y = Cs[row * CSTR + q4 + 1] + bias[n0 + q4 + 1];
        o.z = Cs[row * CSTR + q4 + 2] + bias[n0 + q4 + 2];
        o.w = Cs[row * CSTR + q4 + 3] + bias[n0 + q4 + 3];
        *(float4*)&outp[(size_t)(m0 + row) * DIM + n0 + q4] = o;
    }
}

// ---------------- attention: fp16, 128-q tile, 8 warps, 4-stage cp.async ----
// Q pre-scaled; full tiles use ex2.approx.f16x2 (half the MUFU ops).
#define ASTR 72
#define AQ_BYTES (128 * ASTR * 2)         /* 18432 */
#define AARR (64 * ASTR * 2)              /* 9216 */
#define ASTAGE (2 * AARR)                 /* 18432 */
#define AST0 AQ_BYTES
#define ATT_SMEM (AST0 + 4 * ASTAGE)      /* 92160 */
#define AOSTR 68

__global__ void __launch_bounds__(256, 2) attn_mma()
{
    extern __shared__ char smraw[];
    const uint32_t sb = smem_u32(smraw);
    __half* Qf = (__half*)smraw;
    float* OS = (float*)(smraw + AST0);   // epilogue reuse (34816 <= 73728)

    const int tid = threadIdx.x, lane = tid & 31, wid = tid >> 5;
    const int bh = blockIdx.y;
    const int qbase = blockIdx.x * 128;
    const int lr = lane >> 2, lc = (lane & 3) * 2;

    const int a_row = (lane & 7) + ((lane >> 3) & 1) * 8;
    const int a_kof = (lane >> 4) * 8;
    const int b_row = (lane & 7) + (lane >> 4) * 8;
    const int b_kof = ((lane >> 3) & 1) * 8;

    const __half* gQ = g_qf + (size_t)bh * NSEQ * DH;
    const __half* gK = g_kf + (size_t)bh * NSEQ * DH;
    const __half* gV = g_vf + (size_t)bh * DH * NSEQ;

    // kept key-tile list + full-unmasked flag (uniform per block)
    int list[32]; int full[32]; int nk = 0;
    #pragma unroll
    for (int kt = 0; kt < 32; kt++) {
        int diff = qbase - kt * 64;
        int lo = diff - 63, hi = diff + 127;
        int mn = lo > 0 ? lo : (hi < 0 ? -hi : 0);
        int alo = lo < 0 ? -lo : lo, ahi = hi < 0 ? -hi : hi;
        int mx = alo > ahi ? alo : ahi;
        if (!(mn > 256 && mx <= 1024)) {
            list[nk] = kt;
            full[nk] = (mx <= 256 || mn > 1024) ? 1 : 0;
            nk++;
        }
    }

    auto load_kv = [&](int st, int kt) {
        const int kb = kt * 64;
        uint32_t base = sb + AST0 + st * ASTAGE;
        #pragma unroll
        for (int p = 0; p < 2; p++) {
            int id = tid + p * 256;
            int r = id >> 3, sg = (id & 7) * 8;
            uint32_t so = (r * ASTR + sg) * 2;
            cp16(base + 0 * AARR + so, gK + (size_t)(kb + r) * DH + sg);
            cp16(base + 1 * AARR + so, gV + (size_t)r * NSEQ + kb + sg);
        }
    };

    // load Q tile + first three K/V stages
    #pragma unroll
    for (int p = 0; p < 4; p++) {
        int id = tid + p * 256;
        int r = id >> 3, sg = (id & 7) * 8;
        *(uint4*)&Qf[r * ASTR + sg] = *(const uint4*)&gQ[(size_t)(qbase + r) * DH + sg];
    }
    load_kv(0, list[0]);
    CP_COMMIT();
    if (nk > 1) load_kv(1, list[1]);
    CP_COMMIT();
    if (nk > 2) load_kv(2, list[2]);
    CP_COMMIT();
    __syncthreads();

    // persistent Q fragments
    uint32_t qf[4][4];
    #pragma unroll
    for (int t = 0; t < 4; t++) {
        uint32_t qa = sb + ((wid * 16 + a_row) * ASTR + t * 16 + a_kof) * 2;
        LDM4(qf[t], qa);
    }

    float o[8][4];
    #pragma unroll
    for (int i = 0; i < 8; i++)
        #pragma unroll
        for (int e = 0; e < 4; e++) o[i][e] = 0.f;
    float l0 = 0.f, l1 = 0.f;

    for (int i = 0; i < nk; i++) {
        CP_WAIT2();
        __syncthreads();
        if (i + 3 < nk) load_kv((i + 3) & 3, list[i + 3]);
        CP_COMMIT();

        const int kb = list[i] * 64;
        const uint32_t stb = sb + AST0 + (i & 3) * ASTAGE;

        // S = Q K^T  (Q pre-scaled: S is log2-domain logits)
        float s[8][4];
        #pragma unroll
        for (int j = 0; j < 8; j++)
            #pragma unroll
            for (int e = 0; e < 4; e++) s[j][e] = 0.f;
        #pragma unroll
        for (int t = 0; t < 4; t++) {
            #pragma unroll
            for (int nt2 = 0; nt2 < 4; nt2++) {
                uint32_t k4[4];
                LDM4(k4, stb + ((nt2 * 16 + b_row) * ASTR + t * 16 + b_kof) * 2);
                MMAH(s[2*nt2],     qf[t], k4[0], k4[1]);
                MMAH(s[2*nt2 + 1], qf[t], k4[2], k4[3]);
            }
        }

        // exp2 + row sums; P kept packed fp16 for the PV MMA
        uint32_t pp[8][2];
        float rs0 = 0.f, rs1 = 0.f;
        if (full[i]) {
            #pragma unroll
            for (int nt = 0; nt < 8; nt++) {
                uint32_t a01 = packh2(s[nt][0], s[nt][1]);
                uint32_t a23 = packh2(s[nt][2], s[nt][3]);
                pp[nt][0] = ex2h2(a01);
                pp[nt][1] = ex2h2(a23);
                float2 f0 = __half22float2(*(__half2*)&pp[nt][0]);
                float2 f1 = __half22float2(*(__half2*)&pp[nt][1]);
                rs0 += f0.x + f0.y;
                rs1 += f1.x + f1.y;
            }
        } else {
            const int qr = qbase + wid * 16 + lr;
            #pragma unroll
            for (int nt = 0; nt < 8; nt++) {
                int c = kb + nt * 8 + lc;
                float p[4];
                #pragma unroll
                for (int e = 0; e < 4; e++) {
                    int qi = qr + (e >> 1) * 8;
                    int kj = c + (e & 1);
                    int d = qi - kj; if (d < 0) d = -d;
                    p[e] = (d > 256 && d <= 1024) ? 0.f : ex2(s[nt][e]);
                    if (e < 2) rs0 += p[e]; else rs1 += p[e];
                }
                pp[nt][0] = packh2(p[0], p[1]);
                pp[nt][1] = packh2(p[2], p[3]);
            }
        }
        rs0 += __shfl_xor_sync(0xffffffffu, rs0, 1);
        rs0 += __shfl_xor_sync(0xffffffffu, rs0, 2);
        rs1 += __shfl_xor_sync(0xffffffffu, rs1, 1);
        rs1 += __shfl_xor_sync(0xffffffffu, rs1, 2);
        l0 += rs0; l1 += rs1;

        // O += P V
        #pragma unroll
        for (int t = 0; t < 4; t++) {
            uint32_t ph[4];
            ph[0] = pp[2*t][0];
            ph[1] = pp[2*t][1];
            ph[2] = pp[2*t+1][0];
            ph[3] = pp[2*t+1][1];
            #pragma unroll
            for (int dt2 = 0; dt2 < 4; dt2++) {
                uint32_t vo = ((dt2 * 16 + b_row) * ASTR + t * 16 + b_kof) * 2;
                uint32_t vh4[4];
                LDM4(vh4, stb + 1 * AARR + vo);
                MMAH(o[2*dt2],   ph, vh4[0], vh4[1]);
                MMAH(o[2*dt2+1], ph, vh4[2], vh4[3]);
            }
        }
    }
    __syncthreads();

    // normalize, stage, coalesced fp16 store
    float inv0 = 1.f / l0, inv1 = 1.f / l1;
    #pragma unroll
    for (int dt = 0; dt < 8; dt++)
        #pragma unroll
        for (int e = 0; e < 4; e++) {
            int r = wid * 16 + lr + (e >> 1) * 8;
            int c = dt * 8 + lc + (e & 1);
            OS[r * AOSTR + c] = o[dt][e] * ((e < 2) ? inv0 : inv1);
        }
    __syncthreads();

    const int bb = bh >> 3, hh = bh & 7;
    #pragma unroll
    for (int p = 0; p < 16; p++) {
        int w = tid + p * 256;
        int row = w >> 5, j = w & 31;
        float c0 = OS[row * AOSTR + 2 * j];
        float c1 = OS[row * AOSTR + 2 * j + 1];
        size_t base = ((size_t)(bb * NSEQ + qbase + row)) * INNER + hh * DH + 2 * j;
        *(uint32_t*)(g_ao + base) = packh2(c0, c1);
    }
}

// ---------------------------------------------------------------------------
extern "C" void kernel_launch(void* const* d_in, const int* in_sizes, int n_in,
                              void* d_out, int out_size)
{
    (void)in_sizes; (void)n_in; (void)out_size;
    const float* x     = (const float*)d_in[0];
    const float* w_qkv = (const float*)d_in[1];
    const float* w_out = (const float*)d_in[2];
    const float* b_out = (const float*)d_in[3];
    float* out = (float*)d_out;

    __half *xf, *wqf, *wof, *ao;
    cudaGetSymbolAddress((void**)&xf,  g_xf);
    cudaGetSymbolAddress((void**)&wqf, g_wqf);
    cudaGetSymbolAddress((void**)&wof, g_wof);
    cudaGetSymbolAddress((void**)&ao,  g_ao);

    cudaFuncSetAttribute(gemm_mma, cudaFuncAttributeMaxDynamicSharedMemorySize, GEMM_SMEM);
    cudaFuncSetAttribute(out_gemm, cudaFuncAttributeMaxDynamicSharedMemorySize, OUT_SMEM);
    cudaFuncSetAttribute(attn_mma, cudaFuncAttributeMaxDynamicSharedMemorySize, ATT_SMEM);

    prep_all<<<NBX + NBWQ + NBWO, 256>>>(x, w_qkv, w_out);

    gemm_mma<<<dim3(QKV_N/128, M_TOT/128), 256, GEMM_SMEM>>>(xf, wqf, DIM);

    attn_mma<<<dim3(NSEQ/128, BATCH*H), 256, ATT_SMEM>>>();

    out_gemm<<<dim3(DIM/128, M_TOT/128), 256, OUT_SMEM>>>(
        ao, wof, INNER, b_out, out);
}

// round 16
// speedup vs baseline: 1.0259x; 1.0093x over previous
#include <cuda_runtime.h>
#include <cuda_bf16.h>
#include <cuda_fp16.h>
#include <cstdint>
#include <float.h>

#define BATCH 2
#define NSEQ  2048
#define DIM   512
#define H     8
#define DH    64
#define INNER 512
#define M_TOT 4096
#define QKV_N 1536
#define QSCALE 0.18033688f   /* 0.125 * log2(e) */

// ---------------- device scratch (allocation-free) --------------------------
__device__ __align__(16) __half g_xf[M_TOT*DIM];         // x fp16
__device__ __align__(16) __half g_wqf[QKV_N*DIM];        // w_qkv^T fp16 [N][K]
__device__ __align__(16) __half g_wof[DIM*INNER];        // w_out^T fp16 [N][K]
__device__ __align__(16) __half g_qf[BATCH*H*NSEQ*DH];   // [bh][n][d], pre-scaled
__device__ __align__(16) __half g_kf[BATCH*H*NSEQ*DH];   // [bh][n][d]
__device__ __align__(16) __half g_vf[BATCH*H*DH*NSEQ];   // [bh][d][n] (V^T)
__device__ __align__(16) __half g_ao[M_TOT*INNER];       // [b*n][h*d]

// ---------------- helpers ---------------------------------------------------
#define MMAH(d, a, b0, b1)                                                     \
    asm volatile("mma.sync.aligned.m16n8k16.row.col.f32.f16.f16.f32 "          \
        "{%0,%1,%2,%3},{%4,%5,%6,%7},{%8,%9},{%0,%1,%2,%3};"                   \
        : "+f"((d)[0]), "+f"((d)[1]), "+f"((d)[2]), "+f"((d)[3])               \
        : "r"((a)[0]), "r"((a)[1]), "r"((a)[2]), "r"((a)[3]),                  \
          "r"(b0), "r"(b1))

#define LDM4(r, a)                                                             \
    asm volatile("ldmatrix.sync.aligned.m8n8.x4.shared.b16 {%0,%1,%2,%3}, [%4];" \
        : "=r"((r)[0]), "=r"((r)[1]), "=r"((r)[2]), "=r"((r)[3]) : "r"(a))

__device__ __forceinline__ float ex2(float x) {
    float r;
    asm("ex2.approx.f32 %0, %1;" : "=f"(r) : "f"(x));
    return r;
}
__device__ __forceinline__ uint32_t ex2h2(uint32_t x) {
    uint32_t r;
    asm("ex2.approx.f16x2 %0, %1;" : "=r"(r) : "r"(x));
    return r;
}
__device__ __forceinline__ uint32_t packh2(float a, float b) {
    __half2 h = __floats2half2_rn(a, b);
    return *reinterpret_cast<uint32_t*>(&h);
}
__device__ __forceinline__ uint32_t smem_u32(const void* p) {
    uint32_t a;
    asm("{ .reg .u64 t; cvta.to.shared.u64 t, %1; cvt.u32.u64 %0, t; }"
        : "=r"(a) : "l"(p));
    return a;
}
__device__ __forceinline__ void cp16(uint32_t d, const void* s) {
    asm volatile("cp.async.cg.shared.global [%0], [%1], 16;"
                 :: "r"(d), "l"(s) : "memory");
}
#define CP_COMMIT() asm volatile("cp.async.commit_group;" ::: "memory")
#define CP_WAIT0()  asm volatile("cp.async.wait_group 0;" ::: "memory")
#define CP_WAIT1()  asm volatile("cp.async.wait_group 1;" ::: "memory")
#define CP_WAIT2()  asm volatile("cp.async.wait_group 2;" ::: "memory")

// ---------------- merged prep kernel ----------------------------------------
#define NBX  (M_TOT*DIM/1024)        /* 2048 */
#define NBWQ ((QKV_N/32)*(DIM/32))   /* 768 */
#define NBWO ((DIM/32)*(INNER/32))   /* 256 */

__global__ void __launch_bounds__(256) prep_all(
    const float* __restrict__ x,
    const float* __restrict__ w_qkv,
    const float* __restrict__ w_out)
{
    __shared__ float t[32][33];
    const int b = blockIdx.x, tid = threadIdx.x;

    if (b < NBX) {
        int i = (b * 256 + tid) * 4;
        float4 v = *(const float4*)&x[i];
        uint2 o;
        o.x = packh2(v.x, v.y);
        o.y = packh2(v.z, v.w);
        *(uint2*)&g_xf[i] = o;
        return;
    }

    const float* src; __half* dst; int R, C, l;
    if (b < NBX + NBWQ) {
        l = b - NBX; src = w_qkv; dst = g_wqf; R = DIM; C = QKV_N;
    } else {
        l = b - NBX - NBWQ; src = w_out; dst = g_wof; R = INNER; C = DIM;
    }
    int bx = l % (C / 32), by = l / (C / 32);
    int c0 = bx * 32, r0 = by * 32;
    int xx = tid & 31, yy = tid >> 5;   // 32 x 8
    #pragma unroll
    for (int j = 0; j < 32; j += 8)
        t[yy + j][xx] = src[(size_t)(r0 + yy + j) * C + c0 + xx];
    __syncthreads();
    #pragma unroll
    for (int j = 0; j < 32; j += 8)
        dst[(size_t)(c0 + yy + j) * R + r0 + xx] = __float2half(t[xx][yy + j]);
}

// ---------------- qkv GEMM: 128x128, BK=64, 3-stage, 2 CTA/SM ---------------
#define GSTR 72
#define GARR 18432                    /* 128*GSTR*2 bytes per array */
#define GSTAGE 36864                  /* 2 arrays */
#define CSTR 132
#define GEMM_SMEM 110592              /* 3 stages; Cs (67584) reuses */

__global__ void __launch_bounds__(256, 2) gemm_mma(
    const __half* __restrict__ Ah, const __half* __restrict__ Bh, int K)
{
    extern __shared__ char smraw[];
    const uint32_t sb = smem_u32(smraw);
    float* Cs = (float*)smraw;

    const int tid = threadIdx.x, lane = tid & 31, wid = tid >> 5;
    const int wm = (wid & 3) * 32, wn = (wid >> 2) * 64;
    const int m0 = blockIdx.y * 128, n0 = blockIdx.x * 128;
    const int lr = lane >> 2, lc = (lane & 3) * 2;
    const int nCh = K >> 6;

    const int a_row = (lane & 7) + ((lane >> 3) & 1) * 8;
    const int a_kof = (lane >> 4) * 8;
    const int b_row = (lane & 7) + (lane >> 4) * 8;
    const int b_kof = ((lane >> 3) & 1) * 8;

    float acc[2][8][4];
    #pragma unroll
    for (int i = 0; i < 2; i++)
        #pragma unroll
        for (int j = 0; j < 8; j++)
            #pragma unroll
            for (int e = 0; e < 4; e++) acc[i][j][e] = 0.f;

    auto load_stage = [&](int st, int k0) {
        uint32_t base = sb + st * GSTAGE;
        #pragma unroll
        for (int p = 0; p < 4; p++) {
            int id = tid + p * 256;
            int r = id >> 3, sg = (id & 7) * 8;
            uint32_t so = r * (GSTR * 2) + sg * 2;
            cp16(base + 0 * GARR + so, Ah + (size_t)(m0 + r) * K + k0 + sg);
            cp16(base + 1 * GARR + so, Bh + (size_t)(n0 + r) * K + k0 + sg);
        }
    };

    load_stage(0, 0);
    CP_COMMIT();
    if (nCh > 1) load_stage(1, 64);
    CP_COMMIT();

    for (int c = 0; c < nCh; ++c) {
        CP_WAIT1();
        __syncthreads();
        if (c + 2 < nCh) load_stage((c + 2) % 3, (c + 2) << 6);
        CP_COMMIT();

        const uint32_t stb = sb + (c % 3) * GSTAGE;

        #pragma unroll
        for (int kc = 0; kc < 64; kc += 16) {
            uint32_t ah[2][4];
            #pragma unroll
            for (int mt = 0; mt < 2; mt++) {
                uint32_t ao_ = stb + ((wm + mt * 16 + a_row) * GSTR + kc + a_kof) * 2;
                LDM4(ah[mt], ao_);
            }
            #pragma unroll
            for (int nt2 = 0; nt2 < 4; nt2++) {
                uint32_t bo = stb + ((wn + nt2 * 16 + b_row) * GSTR + kc + b_kof) * 2;
                uint32_t bh4[4];
                LDM4(bh4, bo + 1 * GARR);
                const int n0t = nt2 * 2, n1t = nt2 * 2 + 1;
                MMAH(acc[0][n0t], ah[0], bh4[0], bh4[1]);
                MMAH(acc[1][n0t], ah[1], bh4[0], bh4[1]);
                MMAH(acc[0][n1t], ah[0], bh4[2], bh4[3]);
                MMAH(acc[1][n1t], ah[1], bh4[2], bh4[3]);
            }
        }
    }
    __syncthreads();

    // stage C in smem (fp32)
    #pragma unroll
    for (int mt = 0; mt < 2; mt++)
        #pragma unroll
        for (int nt = 0; nt < 8; nt++)
            #pragma unroll
            for (int e = 0; e < 4; e++) {
                int r = wm + mt * 16 + lr + (e >> 1) * 8;
                int c = wn + nt * 8 + lc + (e & 1);
                Cs[r * CSTR + c] = acc[mt][nt][e];
            }
    __syncthreads();

    // qkv scatter epilogue
    const int t = n0 >> 9, sec = n0 & 511, head0 = sec >> 6;
    const int bb = m0 >> 11, nbase = m0 & (NSEQ - 1);
    if (t < 2) {
        __half* dst = (t == 0) ? g_qf : g_kf;
        const float qs = (t == 0) ? QSCALE : 1.0f;   // fold softmax scale into Q
        #pragma unroll
        for (int p = 0; p < 32; p++) {
            int w = tid + p * 256;
            int row = w >> 6, j = w & 63;
            int head = head0 + (j >> 5), ji = j & 31;
            float c0 = Cs[row * CSTR + 2 * j] * qs;
            float c1 = Cs[row * CSTR + 2 * j + 1] * qs;
            size_t base = ((size_t)(bb * 8 + head) * NSEQ + nbase + row) * DH;
            ((uint32_t*)(dst + base))[ji] = packh2(c0, c1);
        }
    } else {
        // V transposed fp16: [bh][d][n]
        #pragma unroll
        for (int cit = 0; cit < 16; cit++) {
            int col = wid * 16 + cit;
            int head = head0 + (col >> 6), d = col & 63;
            int r0 = lane * 4;
            float v0 = Cs[(r0 + 0) * CSTR + col];
            float v1 = Cs[(r0 + 1) * CSTR + col];
            float v2 = Cs[(r0 + 2) * CSTR + col];
            float v3 = Cs[(r0 + 3) * CSTR + col];
            size_t base = ((size_t)(bb * 8 + head) * DH + d) * NSEQ + nbase + r0;
            ((uint32_t*)(g_vf + base))[0] = packh2(v0, v1);
            ((uint32_t*)(g_vf + base))[1] = packh2(v2, v3);
        }
    }
}

// ---------------- out GEMM: 128x128, BK=128, 2-stage (4 chunks) -------------
#define OSTR 136                      /* 128 K-halves + 8 pad */
#define OARR 34816                    /* 128*OSTR*2 */
#define OSTAGE 69632                  /* 2 arrays */
#define OUT_SMEM 139264               /* 2 stages; Cs (67584) reuses */

__global__ void __launch_bounds__(256) out_gemm(
    const __half* __restrict__ Ah, const __half* __restrict__ Bh,
    int K, const float* __restrict__ bias, float* __restrict__ outp)
{
    extern __shared__ char smraw[];
    const uint32_t sb = smem_u32(smraw);
    float* Cs = (float*)smraw;

    const int tid = threadIdx.x, lane = tid & 31, wid = tid >> 5;
    const int wm = (wid & 3) * 32, wn = (wid >> 2) * 64;
    const int m0 = blockIdx.y * 128, n0 = blockIdx.x * 128;
    const int lr = lane >> 2, lc = (lane & 3) * 2;
    const int nCh = K >> 7;           // BK=128

    const int a_row = (lane & 7) + ((lane >> 3) & 1) * 8;
    const int a_kof = (lane >> 4) * 8;
    const int b_row = (lane & 7) + (lane >> 4) * 8;
    const int b_kof = ((lane >> 3) & 1) * 8;

    float acc[2][8][4];
    #pragma unroll
    for (int i = 0; i < 2; i++)
        #pragma unroll
        for (int j = 0; j < 8; j++)
            #pragma unroll
            for (int e = 0; e < 4; e++) acc[i][j][e] = 0.f;

    auto load_stage = [&](int st, int k0) {
        uint32_t base = sb + st * OSTAGE;
        #pragma unroll
        for (int p = 0; p < 8; p++) {
            int id = tid + p * 256;               // 2048 cp16 per array
            int r = id >> 4, sg = (id & 15) * 8;  // 128 rows x 128 halves
            uint32_t so = r * (OSTR * 2) + sg * 2;
            cp16(base + 0 * OARR + so, Ah + (size_t)(m0 + r) * K + k0 + sg);
            cp16(base + 1 * OARR + so, Bh + (size_t)(n0 + r) * K + k0 + sg);
        }
    };

    load_stage(0, 0);
    CP_COMMIT();

    for (int c = 0; c < nCh; ++c) {
        CP_WAIT0();
        __syncthreads();
        if (c + 1 < nCh) { load_stage((c + 1) & 1, (c + 1) << 7); CP_COMMIT(); }

        const uint32_t stb = sb + (c & 1) * OSTAGE;

        #pragma unroll
        for (int kc = 0; kc < 128; kc += 16) {
            uint32_t ah[2][4];
            #pragma unroll
            for (int mt = 0; mt < 2; mt++) {
                uint32_t ao_ = stb + ((wm + mt * 16 + a_row) * OSTR + kc + a_kof) * 2;
                LDM4(ah[mt], ao_);
            }
            #pragma unroll
            for (int nt2 = 0; nt2 < 4; nt2++) {
                uint32_t bo = stb + ((wn + nt2 * 16 + b_row) * OSTR + kc + b_kof) * 2;
                uint32_t bh4[4];
                LDM4(bh4, bo + 1 * OARR);
                const int n0t = nt2 * 2, n1t = nt2 * 2 + 1;
                MMAH(acc[0][n0t], ah[0], bh4[0], bh4[1]);
                MMAH(acc[1][n0t], ah[1], bh4[0], bh4[1]);
                MMAH(acc[0][n1t], ah[0], bh4[2], bh4[3]);
                MMAH(acc[1][n1t], ah[1], bh4[2], bh4[3]);
            }
        }
    }
    __syncthreads();

    // stage C in smem (fp32)
    #pragma unroll
    for (int mt = 0; mt < 2; mt++)
        #pragma unroll
        for (int nt = 0; nt < 8; nt++)
            #pragma unroll
            for (int e = 0; e < 4; e++) {
                int r = wm + mt * 16 + lr + (e >> 1) * 8;
                int c = wn + nt * 8 + lc + (e & 1);
                Cs[r * CSTR + c] = acc[mt][nt][e];
            }
    __syncthreads();

    #pragma unroll
    for (int p = 0; p < 16; p++) {
        int w = tid + p * 256;
        int row = w >> 5, q4 = (w & 31) * 4;
        float4 o;
        o.x = Cs[row * CSTR + q4 + 0] + bias[n0 + q4 + 0];
        o.y = Cs[row * CSTR + q4 + 1] + bias[n0 + q4 + 1];
        o.z = Cs[row * CSTR + q4 + 2] + bias[n0 + q4 + 2];
        o.w = Cs[row * CSTR + q4 + 3] + bias[n0 + q4 + 3];
        *(float4*)&outp[(size_t)(m0 + row) * DIM + n0 + q4] = o;
    }
}

// ---------------- attention: fp16, 128-q tile, 8 warps, 4-stage cp.async ----
// Q pre-scaled; ex2.approx.f16x2 on full tiles; row-sum shuffles deferred.
#define ASTR 72
#define AQ_BYTES (128 * ASTR * 2)         /* 18432 */
#define AARR (64 * ASTR * 2)              /* 9216 */
#define ASTAGE (2 * AARR)                 /* 18432 */
#define AST0 AQ_BYTES
#define ATT_SMEM (AST0 + 4 * ASTAGE)      /* 92160 */
#define AOSTR 68

__global__ void __launch_bounds__(256, 2) attn_mma()
{
    extern __shared__ char smraw[];
    const uint32_t sb = smem_u32(smraw);
    __half* Qf = (__half*)smraw;
    float* OS = (float*)(smraw + AST0);   // epilogue reuse (34816 <= 73728)

    const int tid = threadIdx.x, lane = tid & 31, wid = tid >> 5;
    const int bh = blockIdx.y;
    const int qbase = blockIdx.x * 128;
    const int lr = lane >> 2, lc = (lane & 3) * 2;

    const int a_row = (lane & 7) + ((lane >> 3) & 1) * 8;
    const int a_kof = (lane >> 4) * 8;
    const int b_row = (lane & 7) + (lane >> 4) * 8;
    const int b_kof = ((lane >> 3) & 1) * 8;

    const __half* gQ = g_qf + (size_t)bh * NSEQ * DH;
    const __half* gK = g_kf + (size_t)bh * NSEQ * DH;
    const __half* gV = g_vf + (size_t)bh * DH * NSEQ;

    // kept key-tile list + full-unmasked flag (uniform per block)
    int list[32]; int full[32]; int nk = 0;
    #pragma unroll
    for (int kt = 0; kt < 32; kt++) {
        int diff = qbase - kt * 64;
        int lo = diff - 63, hi = diff + 127;
        int mn = lo > 0 ? lo : (hi < 0 ? -hi : 0);
        int alo = lo < 0 ? -lo : lo, ahi = hi < 0 ? -hi : hi;
        int mx = alo > ahi ? alo : ahi;
        if (!(mn > 256 && mx <= 1024)) {
            list[nk] = kt;
            full[nk] = (mx <= 256 || mn > 1024) ? 1 : 0;
            nk++;
        }
    }

    auto load_kv = [&](int st, int kt) {
        const int kb = kt * 64;
        uint32_t base = sb + AST0 + st * ASTAGE;
        #pragma unroll
        for (int p = 0; p < 2; p++) {
            int id = tid + p * 256;
            int r = id >> 3, sg = (id & 7) * 8;
            uint32_t so = (r * ASTR + sg) * 2;
            cp16(base + 0 * AARR + so, gK + (size_t)(kb + r) * DH + sg);
            cp16(base + 1 * AARR + so, gV + (size_t)r * NSEQ + kb + sg);
        }
    };

    // load Q tile + first three K/V stages
    #pragma unroll
    for (int p = 0; p < 4; p++) {
        int id = tid + p * 256;
        int r = id >> 3, sg = (id & 7) * 8;
        *(uint4*)&Qf[r * ASTR + sg] = *(const uint4*)&gQ[(size_t)(qbase + r) * DH + sg];
    }
    load_kv(0, list[0]);
    CP_COMMIT();
    if (nk > 1) load_kv(1, list[1]);
    CP_COMMIT();
    if (nk > 2) load_kv(2, list[2]);
    CP_COMMIT();
    __syncthreads();

    // persistent Q fragments
    uint32_t qf[4][4];
    #pragma unroll
    for (int t = 0; t < 4; t++) {
        uint32_t qa = sb + ((wid * 16 + a_row) * ASTR + t * 16 + a_kof) * 2;
        LDM4(qf[t], qa);
    }

    float o[8][4];
    #pragma unroll
    for (int i = 0; i < 8; i++)
        #pragma unroll
        for (int e = 0; e < 4; e++) o[i][e] = 0.f;
    float l0 = 0.f, l1 = 0.f;          // per-thread partials; shuffled ONCE after loop

    for (int i = 0; i < nk; i++) {
        CP_WAIT2();
        __syncthreads();
        if (i + 3 < nk) load_kv((i + 3) & 3, list[i + 3]);
        CP_COMMIT();

        const int kb = list[i] * 64;
        const uint32_t stb = sb + AST0 + (i & 3) * ASTAGE;

        // S = Q K^T  (Q pre-scaled: S is log2-domain logits)
        float s[8][4];
        #pragma unroll
        for (int j = 0; j < 8; j++)
            #pragma unroll
            for (int e = 0; e < 4; e++) s[j][e] = 0.f;
        #pragma unroll
        for (int t = 0; t < 4; t++) {
            #pragma unroll
            for (int nt2 = 0; nt2 < 4; nt2++) {
                uint32_t k4[4];
                LDM4(k4, stb + ((nt2 * 16 + b_row) * ASTR + t * 16 + b_kof) * 2);
                MMAH(s[2*nt2],     qf[t], k4[0], k4[1]);
                MMAH(s[2*nt2 + 1], qf[t], k4[2], k4[3]);
            }
        }

        // exp2 + per-thread row-sum partials; P kept packed fp16
        uint32_t pp[8][2];
        if (full[i]) {
            #pragma unroll
            for (int nt = 0; nt < 8; nt++) {
                uint32_t a01 = packh2(s[nt][0], s[nt][1]);
                uint32_t a23 = packh2(s[nt][2], s[nt][3]);
                pp[nt][0] = ex2h2(a01);
                pp[nt][1] = ex2h2(a23);
                float2 f0 = __half22float2(*(__half2*)&pp[nt][0]);
                float2 f1 = __half22float2(*(__half2*)&pp[nt][1]);
                l0 += f0.x + f0.y;
                l1 += f1.x + f1.y;
            }
        } else {
            const int qr = qbase + wid * 16 + lr;
            #pragma unroll
            for (int nt = 0; nt < 8; nt++) {
                int c = kb + nt * 8 + lc;
                float p[4];
                #pragma unroll
                for (int e = 0; e < 4; e++) {
                    int qi = qr + (e >> 1) * 8;
                    int kj = c + (e & 1);
                    int d = qi - kj; if (d < 0) d = -d;
                    p[e] = (d > 256 && d <= 1024) ? 0.f : ex2(s[nt][e]);
                    if (e < 2) l0 += p[e]; else l1 += p[e];
                }
                pp[nt][0] = packh2(p[0], p[1]);
                pp[nt][1] = packh2(p[2], p[3]);
            }
        }

        // O += P V
        #pragma unroll
        for (int t = 0; t < 4; t++) {
            uint32_t ph[4];
            ph[0] = pp[2*t][0];
            ph[1] = pp[2*t][1];
            ph[2] = pp[2*t+1][0];
            ph[3] = pp[2*t+1][1];
            #pragma unroll
            for (int dt2 = 0; dt2 < 4; dt2++) {
                uint32_t vo = ((dt2 * 16 + b_row) * ASTR + t * 16 + b_kof) * 2;
                uint32_t vh4[4];
                LDM4(vh4, stb + 1 * AARR + vo);
                MMAH(o[2*dt2],   ph, vh4[0], vh4[1]);
                MMAH(o[2*dt2+1], ph, vh4[2], vh4[3]);
            }
        }
    }

    // single deferred row-sum reduction (quad lanes share a row)
    l0 += __shfl_xor_sync(0xffffffffu, l0, 1);
    l0 += __shfl_xor_sync(0xffffffffu, l0, 2);
    l1 += __shfl_xor_sync(0xffffffffu, l1, 1);
    l1 += __shfl_xor_sync(0xffffffffu, l1, 2);
    __syncthreads();

    // normalize, stage, coalesced fp16 store
    float inv0 = 1.f / l0, inv1 = 1.f / l1;
    #pragma unroll
    for (int dt = 0; dt < 8; dt++)
        #pragma unroll
        for (int e = 0; e < 4; e++) {
            int r = wid * 16 + lr + (e >> 1) * 8;
            int c = dt * 8 + lc + (e & 1);
            OS[r * AOSTR + c] = o[dt][e] * ((e < 2) ? inv0 : inv1);
        }
    __syncthreads();

    const int bb = bh >> 3, hh = bh & 7;
    #pragma unroll
    for (int p = 0; p < 16; p++) {
        int w = tid + p * 256;
        int row = w >> 5, j = w & 31;
        float c0 = OS[row * AOSTR + 2 * j];
        float c1 = OS[row * AOSTR + 2 * j + 1];
        size_t base = ((size_t)(bb * NSEQ + qbase + row)) * INNER + hh * DH + 2 * j;
        *(uint32_t*)(g_ao + base) = packh2(c0, c1);
    }
}

// ---------------------------------------------------------------------------
extern "C" void kernel_launch(void* const* d_in, const int* in_sizes, int n_in,
                              void* d_out, int out_size)
{
    (void)in_sizes; (void)n_in; (void)out_size;
    const float* x     = (const float*)d_in[0];
    const float* w_qkv = (const float*)d_in[1];
    const float* w_out = (const float*)d_in[2];
    const float* b_out = (const float*)d_in[3];
    float* out = (float*)d_out;

    __half *xf, *wqf, *wof, *ao;
    cudaGetSymbolAddress((void**)&xf,  g_xf);
    cudaGetSymbolAddress((void**)&wqf, g_wqf);
    cudaGetSymbolAddress((void**)&wof, g_wof);
    cudaGetSymbolAddress((void**)&ao,  g_ao);

    cudaFuncSetAttribute(gemm_mma, cudaFuncAttributeMaxDynamicSharedMemorySize, GEMM_SMEM);
    cudaFuncSetAttribute(out_gemm, cudaFuncAttributeMaxDynamicSharedMemorySize, OUT_SMEM);
    cudaFuncSetAttribute(attn_mma, cudaFuncAttributeMaxDynamicSharedMemorySize, ATT_SMEM);

    prep_all<<<NBX + NBWQ + NBWO, 256>>>(x, w_qkv, w_out);

    gemm_mma<<<dim3(QKV_N/128, M_TOT/128), 256, GEMM_SMEM>>>(xf, wqf, DIM);

    attn_mma<<<dim3(NSEQ/128, BATCH*H), 256, ATT_SMEM>>>();

    out_gemm<<<dim3(DIM/128, M_TOT/128), 256, OUT_SMEM>>>(
        ao, wof, INNER, b_out, out);
}